// round 13
// baseline (speedup 1.0000x reference)
#include <cuda_runtime.h>
#include <cuda_fp16.h>
#include <math.h>
#include <stdint.h>

// ---------------- problem constants ----------------
#define T_TOK 8192
#define HID   1024
#define NEXP  64
#define KTOP  2
#define CAP   1024
#define FFN   512
#define SFFN  1024
#define NASSIGN (T_TOK*KTOP)
#define RKS   4            // router K slices

// ---------------- helpers (compute_103-safe PTX only) ----------------
__device__ __forceinline__ uint32_t smem_u32(const void* p) {
    uint32_t a;
    asm("{ .reg .u64 t; cvta.to.shared.u64 t, %1; cvt.u32.u64 %0, t; }" : "=r"(a) : "l"(p));
    return a;
}
__device__ __forceinline__ void ldm_x4(uint32_t addr, uint32_t& r0, uint32_t& r1,
                                       uint32_t& r2, uint32_t& r3) {
    asm volatile("ldmatrix.sync.aligned.m8n8.x4.shared.b16 {%0,%1,%2,%3}, [%4];"
        : "=r"(r0), "=r"(r1), "=r"(r2), "=r"(r3) : "r"(addr));
}
__device__ __forceinline__ void ldm_x4t(uint32_t addr, uint32_t& r0, uint32_t& r1,
                                        uint32_t& r2, uint32_t& r3) {
    asm volatile("ldmatrix.sync.aligned.m8n8.x4.trans.shared.b16 {%0,%1,%2,%3}, [%4];"
        : "=r"(r0), "=r"(r1), "=r"(r2), "=r"(r3) : "r"(addr));
}
__device__ __forceinline__ void mma_fp16(float* d, const uint32_t* a, uint32_t b0, uint32_t b1) {
    asm volatile("mma.sync.aligned.m16n8k16.row.col.f32.f16.f16.f32 "
        "{%0,%1,%2,%3}, {%4,%5,%6,%7}, {%8,%9}, {%0,%1,%2,%3};"
        : "+f"(d[0]), "+f"(d[1]), "+f"(d[2]), "+f"(d[3])
        : "r"(a[0]), "r"(a[1]), "r"(a[2]), "r"(a[3]), "r"(b0), "r"(b1));
}
__device__ __forceinline__ void cp16(uint32_t dst, const void* src) {
    size_t g = __cvta_generic_to_global(src);
    asm volatile("cp.async.cg.shared.global [%0], [%1], 16;" :: "r"(dst), "l"(g));
}
#define CP_COMMIT() asm volatile("cp.async.commit_group;" ::: "memory")
#define CP_WAIT1()  asm volatile("cp.async.wait_group 1;" ::: "memory")
// A tiles: 128B rows -> chunk[4:6] ^= row&7
#define SWA(o) ((o) ^ (((o) >> 3) & 0x70))
// B tiles: 256B rows -> chunk[4:6] ^= k&7
#define SWB(o) ((o) ^ (((o) >> 4) & 0x70))

// ---------------- scratch (device globals; allocation is forbidden) ----------
__device__ float g_part[RKS * T_TOK * NEXP];       // router split-K partials, 8 MB
__device__ float g_topv[NASSIGN];
__device__ int   g_listcnt[NEXP];
__device__ float g_psum[NEXP];
__device__ int   g_assign[NEXP * CAP];

__device__ __align__(16) __half g_xh[T_TOK * HID];                  // 16 MB
__device__ __align__(16) __half g_w1h[(size_t)NEXP * HID * FFN];    // 64 MB
__device__ __align__(16) __half g_w2h[(size_t)NEXP * FFN * HID];    // 64 MB
__device__ __align__(16) __half g_ws1h[(size_t)HID * SFFN];
__device__ __align__(16) __half g_ws2h[(size_t)SFFN * HID];
__device__ __align__(16) __half g_h[(size_t)NEXP * CAP * FFN];      // 64 MB
__device__ __align__(16) __half g_s[(size_t)T_TOK * SFFN];          // 16 MB

// fast gelu: tanh via __expf (error ~1e-6, invisible under fp16-pass budget)
__device__ __forceinline__ float gelu_f(float x) {
    float z = 0.7978845608028654f * (x + 0.044715f * x * x * x);
    float t = __expf(2.0f * z);
    float th = 1.0f - 2.0f / (t + 1.0f);
    return 0.5f * x * (1.0f + th);
}

// ---------------- merged prepass: all fp32 -> fp16 conversions + zeroing ------
__device__ __forceinline__ uint2 pack4(float4 v) {
    uint2 r;
    __half2 a = __floats2half2_rn(v.x, v.y);
    __half2 b = __floats2half2_rn(v.z, v.w);
    r.x = *reinterpret_cast<uint32_t*>(&a);
    r.y = *reinterpret_cast<uint32_t*>(&b);
    return r;
}
// block partition over 2048 blocks: x 224 | w1 880 | w2 880 | ws1 32 | ws2 32
__global__ void cvt_all(const float4* __restrict__ x,  uint2* __restrict__ xo,
                        const float4* __restrict__ w1, uint2* __restrict__ w1o,
                        const float4* __restrict__ w2, uint2* __restrict__ w2o,
                        const float4* __restrict__ s1, uint2* __restrict__ s1o,
                        const float4* __restrict__ s2, uint2* __restrict__ s2o)
{
    if (blockIdx.x == 0 && threadIdx.x < NEXP) {
        g_listcnt[threadIdx.x] = 0;
        g_psum[threadIdx.x] = 0.0f;
    }
    int b = blockIdx.x;
    const float4* in; uint2* out; int n, b0, bc;
    if (b < 224)       { in = x;  out = xo;  n = 2097152; b0 = 0;    bc = 224; }
    else if (b < 1104) { in = w1; out = w1o; n = 8388608; b0 = 224;  bc = 880; }
    else if (b < 1984) { in = w2; out = w2o; n = 8388608; b0 = 1104; bc = 880; }
    else if (b < 2016) { in = s1; out = s1o; n = 262144;  b0 = 1984; bc = 32;  }
    else               { in = s2; out = s2o; n = 262144;  b0 = 2016; bc = 32;  }
    int g = bc * 256;
    int i = (b - b0) * 256 + threadIdx.x;
    for (; i + 3 * g < n; i += 4 * g) {
        float4 v0 = in[i], v1 = in[i + g], v2 = in[i + 2 * g], v3 = in[i + 3 * g];
        out[i]         = pack4(v0);
        out[i + g]     = pack4(v1);
        out[i + 2 * g] = pack4(v2);
        out[i + 3 * g] = pack4(v3);
    }
    for (; i < n; i += g) out[i] = pack4(in[i]);
}

// ---------------- exact fp32 router GEMM, split-K into RKS slices ------------
#define RTM 64
#define RTK 16
__global__ void router_sgemm(const float* __restrict__ A, const float* __restrict__ B)
{
    __shared__ float As[RTK][RTM + 4];
    __shared__ float Bs[RTK][64];
    int tid = threadIdx.x;
    int tx = tid & 15, ty = tid >> 4;
    int bm = blockIdx.y * RTM;
    int z  = blockIdx.z;                        // K slice
    float* Cc = g_part + z * T_TOK * NEXP;
    int la_m = tid >> 2, la_k = (tid & 3) * 4;
    int lb_k = tid >> 4, lb_n = (tid & 15) * 4;
    float acc[4][4];
#pragma unroll
    for (int i = 0; i < 4; i++)
#pragma unroll
        for (int j = 0; j < 4; j++) acc[i][j] = 0.0f;
    const int kbeg = z * (HID / RKS), kend = kbeg + HID / RKS;
    for (int k0 = kbeg; k0 < kend; k0 += RTK) {
        float4 av = *reinterpret_cast<const float4*>(A + (size_t)(bm + la_m) * HID + k0 + la_k);
        As[la_k + 0][la_m] = av.x; As[la_k + 1][la_m] = av.y;
        As[la_k + 2][la_m] = av.z; As[la_k + 3][la_m] = av.w;
        float4 bv = *reinterpret_cast<const float4*>(B + (size_t)(k0 + lb_k) * NEXP + lb_n);
        Bs[lb_k][lb_n + 0] = bv.x; Bs[lb_k][lb_n + 1] = bv.y;
        Bs[lb_k][lb_n + 2] = bv.z; Bs[lb_k][lb_n + 3] = bv.w;
        __syncthreads();
#pragma unroll
        for (int kk = 0; kk < RTK; kk++) {
            float a[4], b[4];
#pragma unroll
            for (int i = 0; i < 4; i++) a[i] = As[kk][ty * 4 + i];
#pragma unroll
            for (int j = 0; j < 4; j++) b[j] = Bs[kk][tx * 4 + j];
#pragma unroll
            for (int i = 0; i < 4; i++)
#pragma unroll
                for (int j = 0; j < 4; j++) acc[i][j] += a[i] * b[j];
        }
        __syncthreads();
    }
#pragma unroll
    for (int i = 0; i < 4; i++)
#pragma unroll
        for (int j = 0; j < 4; j++)
            Cc[(size_t)(bm + ty * 4 + i) * NEXP + tx * 4 + j] = acc[i][j];
}

// ---------------- router top-k / softmax / slot assignment (fused) ----------
__global__ void topk_kernel() {
    int warp = threadIdx.x >> 5, lane = threadIdx.x & 31;
    int t = blockIdx.x * 4 + warp;
    if (t >= T_TOK) return;
    float s0 = 0.0f, s1 = 0.0f;
#pragma unroll
    for (int z = 0; z < RKS; z++) {
        s0 += g_part[z * T_TOK * NEXP + t * NEXP + lane];
        s1 += g_part[z * T_TOK * NEXP + t * NEXP + 32 + lane];
    }
    float m = fmaxf(s0, s1);
#pragma unroll
    for (int o = 16; o; o >>= 1) m = fmaxf(m, __shfl_xor_sync(0xffffffffu, m, o));
    float e0 = expf(s0 - m), e1 = expf(s1 - m);
    float d = e0 + e1;
#pragma unroll
    for (int o = 16; o; o >>= 1) d += __shfl_xor_sync(0xffffffffu, d, o);
    float p0 = e0 / d, p1 = e1 / d;

    float mx = fmaxf(p0, p1);
#pragma unroll
    for (int o = 16; o; o >>= 1) mx = fmaxf(mx, __shfl_xor_sync(0xffffffffu, mx, o));
    int cand = 0x7fffffff;
    if (p0 == mx) cand = lane;
    if (p1 == mx) cand = min(cand, lane + 32);
#pragma unroll
    for (int o = 16; o; o >>= 1) cand = min(cand, __shfl_xor_sync(0xffffffffu, cand, o));
    int i1 = cand; float v1 = mx;

    float q0 = (lane == i1) ? -1e30f : p0;
    float q1 = (lane + 32 == i1) ? -1e30f : p1;
    float mx2 = fmaxf(q0, q1);
#pragma unroll
    for (int o = 16; o; o >>= 1) mx2 = fmaxf(mx2, __shfl_xor_sync(0xffffffffu, mx2, o));
    int cand2 = 0x7fffffff;
    if (q0 == mx2) cand2 = lane;
    if (q1 == mx2) cand2 = min(cand2, lane + 32);
#pragma unroll
    for (int o = 16; o; o >>= 1) cand2 = min(cand2, __shfl_xor_sync(0xffffffffu, cand2, o));
    int i2 = cand2; float v2 = mx2;

    if (lane == 0) {
        g_topv[t * 2 + 0] = v1;
        g_topv[t * 2 + 1] = v2;
        int p1s = atomicAdd(&g_listcnt[i1], 1);
        if (p1s < CAP) g_assign[i1 * CAP + p1s] = t * 2;
        int p2s = atomicAdd(&g_listcnt[i2], 1);
        if (p2s < CAP) g_assign[i2 * CAP + p2s] = t * 2 + 1;
    }
    atomicAdd(&g_psum[lane], p0);
    atomicAdd(&g_psum[lane + 32], p1);
}

// ---------------- fp16 single-pass mma.sync GEMM (hoisted ldmatrix addrs) ----
// C[M,N] = A[M,K] @ B[K,N]   (B row-major [K][N], loaded via ldmatrix.trans)
// CTA 128x128, K-chunk 64, 3-stage cp.async pipeline, 8 warps (warp tile 64x32).
// EPI: 0 = gelu -> fp16 out, 1 = f32 store, 2 = atomic combine into out[token]
#define STAGE_BYTES 32768   // A 16K + B 16K
#define MISC_OFF    98304   // 3 stages

template<int EPI, bool GATHER, bool EXPERT>
__global__ void __launch_bounds__(256, 2)
mma_gemm(const __half* __restrict__ A, int lda, long aBatch,
         const __half* __restrict__ B, int ldb, long bBatch,
         __half* __restrict__ outH, float* __restrict__ outF, int ldc, long cBatch,
         int M, int Kd)
{
    extern __shared__ char smem[];
    const int tid = threadIdx.x;
    const int lane = tid & 31, warp = tid >> 5;
    const int wm = warp & 1, wn = warp >> 1;
    const int bm = blockIdx.y * 128, bn = blockIdx.x * 128;

    int e = 0, cnt = M;
    if (EXPERT) {
        e = blockIdx.z;
        cnt = min(g_listcnt[e], CAP);
        if (bm >= cnt) return;
        if (aBatch) A += (size_t)e * aBatch;
        B += (size_t)e * bBatch;
        if (EPI == 0) outH += (size_t)e * cBatch;
    }

    int*   tok = (int*)(smem + MISC_OFF);
    float* pw  = (float*)(smem + MISC_OFF + 512);
    if ((GATHER || EPI == 2) && tid < 128) {
        int idx = min(bm + tid, cnt - 1);
        int a = g_assign[e * CAP + idx];
        tok[tid] = a >> 1;                    // token (KTOP=2)
        pw[tid]  = g_topv[a];
    }
    __syncthreads();

    uint32_t sb = smem_u32(smem);
    const int NC = Kd >> 6;

    // hoisted per-thread cp.async source offsets & smem targets
    const char* Ab = (const char*)A;
    const char* Bb = (const char*)B;
    size_t offA[4]; uint32_t soA[4];
    size_t offB[4]; uint32_t soB[4];
#pragma unroll
    for (int j = 0; j < 4; j++) {
        int p = tid + j * 256;
        int r = p >> 3, q = p & 7;                 // A: 128 rows x 8 vec16
        size_t row = GATHER ? (size_t)tok[r] : (size_t)(bm + r);
        offA[j] = (row * lda + q * 8) * 2;
        soA[j]  = SWA((uint32_t)(r * 128 + q * 16));
        int kr = p >> 4, nq = p & 15;              // B: 64 rows x 16 vec16
        offB[j] = ((size_t)kr * ldb + bn + nq * 8) * 2;
        soB[j]  = 16384 + SWB((uint32_t)(kr * 256 + nq * 16));
    }
    const size_t stepA = 64 * 2;
    const size_t stepB = (size_t)64 * ldb * 2;

    // hoisted ldmatrix address invariants:
    //   A: addr(kk) = sA + (aInv[mt] ^ (kk*32))   (XOR legal: no carries into mask bits)
    //   B: addr(kk) = sA + bInv[ntp] + kk*4096    (mask depends only on lane&15)
    uint32_t aInv[4], bInv[2];
#pragma unroll
    for (int mt = 0; mt < 4; mt++) {
        uint32_t row = wm * 64 + mt * 16 + (lane & 15);
        uint32_t col = (lane >> 4) << 4;
        aInv[mt] = row * 128 + (col ^ ((row & 7) << 4));
    }
#pragma unroll
    for (int ntp = 0; ntp < 2; ntp++) {
        uint32_t o = (lane & 15) * 256 + (wn * 32 + ntp * 16 + ((lane >> 4) << 3)) * 2;
        bInv[ntp] = 16384 + SWB(o);
    }

#define ISSUE_CHUNK(ss) do {                                                  \
    uint32_t st_ = sb + (ss) * STAGE_BYTES;                                   \
    _Pragma("unroll")                                                         \
    for (int j = 0; j < 4; j++) {                                             \
        cp16(st_ + soA[j], Ab + offA[j]);  offA[j] += stepA;                  \
        cp16(st_ + soB[j], Bb + offB[j]);  offB[j] += stepB;                  \
    } } while (0)

    ISSUE_CHUNK(0); CP_COMMIT();
    ISSUE_CHUNK(1); CP_COMMIT();

    float acc[4][4][4];
#pragma unroll
    for (int a = 0; a < 4; a++)
#pragma unroll
        for (int b = 0; b < 4; b++)
#pragma unroll
            for (int c = 0; c < 4; c++) acc[a][b][c] = 0.0f;

    for (int c = 0; c < NC; ++c) {
        CP_WAIT1();
        __syncthreads();
        if (c + 2 < NC) { ISSUE_CHUNK((c + 2) % 3); }
        CP_COMMIT();
        uint32_t sA = sb + (c % 3) * STAGE_BYTES;
#pragma unroll
        for (int kk = 0; kk < 4; kk++) {
            uint32_t af[4][4];
#pragma unroll
            for (int mt = 0; mt < 4; mt++)
                ldm_x4(sA + (aInv[mt] ^ (kk * 32)),
                       af[mt][0], af[mt][1], af[mt][2], af[mt][3]);
#pragma unroll
            for (int ntp = 0; ntp < 2; ntp++) {
                uint32_t b0, b1, b2, b3;
                ldm_x4t(sA + bInv[ntp] + kk * 4096, b0, b1, b2, b3);
#pragma unroll
                for (int mt = 0; mt < 4; mt++) {
                    mma_fp16(acc[mt][ntp * 2],     af[mt], b0, b1);
                    mma_fp16(acc[mt][ntp * 2 + 1], af[mt], b2, b3);
                }
            }
        }
    }
#undef ISSUE_CHUNK

    const int gr = lane >> 2, gc = (lane & 3) * 2;
    if (EPI == 2) {
        __syncthreads();
        float* tile = (float*)smem;   // 128x128 f32 = 64KB
#pragma unroll
        for (int mt = 0; mt < 4; mt++)
#pragma unroll
            for (int nt = 0; nt < 4; nt++)
#pragma unroll
                for (int h = 0; h < 2; h++) {
                    int rl = wm * 64 + mt * 16 + gr + h * 8;
                    int cl = wn * 32 + nt * 8 + gc;
                    *reinterpret_cast<float2*>(&tile[rl * 128 + cl]) =
                        make_float2(acc[mt][nt][2 * h], acc[mt][nt][2 * h + 1]);
                }
        __syncthreads();
        for (int r = warp; r < 128; r += 8) {
            if (bm + r < cnt) {
                float p = pw[r];
                float* base = outF + (size_t)tok[r] * HID + bn;
                for (int cc = lane; cc < 128; cc += 32)
                    atomicAdd(base + cc, p * tile[r * 128 + cc]);
            }
        }
    } else {
#pragma unroll
        for (int mt = 0; mt < 4; mt++)
#pragma unroll
            for (int nt = 0; nt < 4; nt++)
#pragma unroll
                for (int h = 0; h < 2; h++) {
                    int r = bm + wm * 64 + mt * 16 + gr + h * 8;
                    if (r >= cnt) continue;
                    int col = bn + wn * 32 + nt * 8 + gc;
                    if (EPI == 0) {
                        __half2 hv = __floats2half2_rn(gelu_f(acc[mt][nt][2 * h]),
                                                       gelu_f(acc[mt][nt][2 * h + 1]));
                        *reinterpret_cast<__half2*>(outH + (size_t)r * ldc + col) = hv;
                    } else {
                        *reinterpret_cast<float2*>(outF + (size_t)r * ldc + col) =
                            make_float2(acc[mt][nt][2 * h], acc[mt][nt][2 * h + 1]);
                    }
                }
    }
}

// ---------------- aux loss (listcnt doubles as pre-capacity counts) ----------
__global__ void aux_kernel(float* __restrict__ out, int out_size)
{
    __shared__ float vals[NEXP];
    int i = threadIdx.x;
    if (i < NEXP) {
        float f = (float)g_listcnt[i] / (float)(T_TOK * KTOP);
        float P = g_psum[i] / (float)T_TOK;
        vals[i] = f * P;
    }
    __syncthreads();
    if (i == 0) {
        float s = 0.0f;
        for (int j = 0; j < NEXP; j++) s += vals[j];
        if (out_size > T_TOK * HID) out[T_TOK * HID] = 0.01f * (float)NEXP * s;
    }
}

// ---------------- launch ----------------
extern "C" void kernel_launch(void* const* d_in, const int* in_sizes, int n_in,
                              void* d_out, int out_size)
{
    const float* x        = (const float*)d_in[0];  // [T,H]
    const float* w_router = (const float*)d_in[1];  // [H,E]
    const float* w1       = (const float*)d_in[2];  // [E,H,F]
    const float* w2       = (const float*)d_in[3];  // [E,F,H]
    const float* ws1      = (const float*)d_in[4];  // [H,SF]
    const float* ws2      = (const float*)d_in[5];  // [SF,H]
    float* out = (float*)d_out;

    __half *xh, *w1h, *w2h, *ws1h, *ws2h, *hbuf, *sbuf;
    cudaGetSymbolAddress((void**)&xh,  g_xh);
    cudaGetSymbolAddress((void**)&w1h, g_w1h);
    cudaGetSymbolAddress((void**)&w2h, g_w2h);
    cudaGetSymbolAddress((void**)&ws1h, g_ws1h);
    cudaGetSymbolAddress((void**)&ws2h, g_ws2h);
    cudaGetSymbolAddress((void**)&hbuf, g_h);
    cudaGetSymbolAddress((void**)&sbuf, g_s);

    const int SMB = MISC_OFF + 1024;   // 3 stages + tok/pw
    cudaFuncSetAttribute(mma_gemm<0, true,  true >, cudaFuncAttributeMaxDynamicSharedMemorySize, SMB);
    cudaFuncSetAttribute(mma_gemm<2, false, true >, cudaFuncAttributeMaxDynamicSharedMemorySize, SMB);
    cudaFuncSetAttribute(mma_gemm<0, false, false>, cudaFuncAttributeMaxDynamicSharedMemorySize, SMB);
    cudaFuncSetAttribute(mma_gemm<1, false, false>, cudaFuncAttributeMaxDynamicSharedMemorySize, SMB);

    // ---- merged prepass (all conversions + bookkeeping zero) ----
    cvt_all<<<2048, 256>>>((const float4*)x,   (uint2*)xh,
                           (const float4*)w1,  (uint2*)w1h,
                           (const float4*)w2,  (uint2*)w2h,
                           (const float4*)ws1, (uint2*)ws1h,
                           (const float4*)ws2, (uint2*)ws2h);

    // ---- router (exact fp32, split-K x4) + fused routing ----
    router_sgemm<<<dim3(1, T_TOK / RTM, RKS), 256>>>(x, w_router);
    topk_kernel<<<T_TOK / 4, 128>>>();

    // ---- shared expert (writes base of out) ----
    mma_gemm<0, false, false><<<dim3(SFFN / 128, T_TOK / 128), 256, SMB>>>(
        xh, HID, 0, ws1h, SFFN, 0, sbuf, nullptr, SFFN, 0, T_TOK, HID);
    mma_gemm<1, false, false><<<dim3(HID / 128, T_TOK / 128), 256, SMB>>>(
        sbuf, SFFN, 0, ws2h, HID, 0, nullptr, out, HID, 0, T_TOK, SFFN);

    // ---- expert MLP; gemm2 atomically combines into out ----
    mma_gemm<0, true, true><<<dim3(FFN / 128, CAP / 128, NEXP), 256, SMB>>>(
        xh, HID, 0, w1h, FFN, (long)HID * FFN, hbuf, nullptr, FFN, (long)CAP * FFN,
        CAP, HID);
    mma_gemm<2, false, true><<<dim3(HID / 128, CAP / 128, NEXP), 256, SMB>>>(
        hbuf, FFN, (long)CAP * FFN, w2h, HID, (long)FFN * HID,
        nullptr, out, HID, 0, CAP, FFN);

    aux_kernel<<<1, 64>>>(out, out_size);
}

// round 14
// speedup vs baseline: 1.0259x; 1.0259x over previous
#include <cuda_runtime.h>
#include <cuda_fp16.h>
#include <math.h>
#include <stdint.h>

// ---------------- problem constants ----------------
#define T_TOK 8192
#define HID   1024
#define NEXP  64
#define KTOP  2
#define CAP   1024
#define FFN   512
#define SFFN  1024
#define NASSIGN (T_TOK*KTOP)
#define RKS   4            // router K slices

// ---------------- helpers (compute_103-safe PTX only) ----------------
__device__ __forceinline__ uint32_t smem_u32(const void* p) {
    uint32_t a;
    asm("{ .reg .u64 t; cvta.to.shared.u64 t, %1; cvt.u32.u64 %0, t; }" : "=r"(a) : "l"(p));
    return a;
}
__device__ __forceinline__ void ldm_x4(uint32_t addr, uint32_t& r0, uint32_t& r1,
                                       uint32_t& r2, uint32_t& r3) {
    asm volatile("ldmatrix.sync.aligned.m8n8.x4.shared.b16 {%0,%1,%2,%3}, [%4];"
        : "=r"(r0), "=r"(r1), "=r"(r2), "=r"(r3) : "r"(addr));
}
__device__ __forceinline__ void ldm_x4t(uint32_t addr, uint32_t& r0, uint32_t& r1,
                                        uint32_t& r2, uint32_t& r3) {
    asm volatile("ldmatrix.sync.aligned.m8n8.x4.trans.shared.b16 {%0,%1,%2,%3}, [%4];"
        : "=r"(r0), "=r"(r1), "=r"(r2), "=r"(r3) : "r"(addr));
}
__device__ __forceinline__ void mma_fp16(float* d, const uint32_t* a, uint32_t b0, uint32_t b1) {
    asm volatile("mma.sync.aligned.m16n8k16.row.col.f32.f16.f16.f32 "
        "{%0,%1,%2,%3}, {%4,%5,%6,%7}, {%8,%9}, {%0,%1,%2,%3};"
        : "+f"(d[0]), "+f"(d[1]), "+f"(d[2]), "+f"(d[3])
        : "r"(a[0]), "r"(a[1]), "r"(a[2]), "r"(a[3]), "r"(b0), "r"(b1));
}
__device__ __forceinline__ void cp16(uint32_t dst, const void* src) {
    size_t g = __cvta_generic_to_global(src);
    asm volatile("cp.async.cg.shared.global [%0], [%1], 16;" :: "r"(dst), "l"(g));
}
#define CP_COMMIT() asm volatile("cp.async.commit_group;" ::: "memory")
#define CP_WAIT1()  asm volatile("cp.async.wait_group 1;" ::: "memory")
// A tiles: 128B rows -> chunk[4:6] ^= row&7
#define SWA(o) ((o) ^ (((o) >> 3) & 0x70))
// B tiles: 256B rows -> chunk[4:6] ^= k&7
#define SWB(o) ((o) ^ (((o) >> 4) & 0x70))

// ---------------- scratch (device globals; allocation is forbidden) ----------
__device__ float g_part[RKS * T_TOK * NEXP];       // router split-K partials, 8 MB
__device__ float g_topv[NASSIGN];
__device__ int   g_listcnt[NEXP];
__device__ float g_psum[NEXP];
__device__ int   g_assign[NEXP * CAP];

__device__ __align__(16) __half g_xh[T_TOK * HID];                  // 16 MB
__device__ __align__(16) __half g_w1h[(size_t)NEXP * HID * FFN];    // 64 MB
__device__ __align__(16) __half g_w2h[(size_t)NEXP * FFN * HID];    // 64 MB
__device__ __align__(16) __half g_ws1h[(size_t)HID * SFFN];
__device__ __align__(16) __half g_ws2h[(size_t)SFFN * HID];
__device__ __align__(16) __half g_h[(size_t)NEXP * CAP * FFN];      // 64 MB
__device__ __align__(16) __half g_s[(size_t)T_TOK * SFFN];          // 16 MB

// fast gelu: tanh via __expf (error ~1e-6, invisible under fp16-pass budget)
__device__ __forceinline__ float gelu_f(float x) {
    float z = 0.7978845608028654f * (x + 0.044715f * x * x * x);
    float t = __expf(2.0f * z);
    float th = 1.0f - 2.0f / (t + 1.0f);
    return 0.5f * x * (1.0f + th);
}

// ---------------- merged prepass: all fp32 -> fp16 conversions + zeroing ------
__device__ __forceinline__ uint2 pack4(float4 v) {
    uint2 r;
    __half2 a = __floats2half2_rn(v.x, v.y);
    __half2 b = __floats2half2_rn(v.z, v.w);
    r.x = *reinterpret_cast<uint32_t*>(&a);
    r.y = *reinterpret_cast<uint32_t*>(&b);
    return r;
}
// block partition over 2048 blocks: x 224 | w1 880 | w2 880 | ws1 32 | ws2 32
__global__ void cvt_all(const float4* __restrict__ x,  uint2* __restrict__ xo,
                        const float4* __restrict__ w1, uint2* __restrict__ w1o,
                        const float4* __restrict__ w2, uint2* __restrict__ w2o,
                        const float4* __restrict__ s1, uint2* __restrict__ s1o,
                        const float4* __restrict__ s2, uint2* __restrict__ s2o)
{
    if (blockIdx.x == 0 && threadIdx.x < NEXP) {
        g_listcnt[threadIdx.x] = 0;
        g_psum[threadIdx.x] = 0.0f;
    }
    int b = blockIdx.x;
    const float4* in; uint2* out; int n, b0, bc;
    if (b < 224)       { in = x;  out = xo;  n = 2097152; b0 = 0;    bc = 224; }
    else if (b < 1104) { in = w1; out = w1o; n = 8388608; b0 = 224;  bc = 880; }
    else if (b < 1984) { in = w2; out = w2o; n = 8388608; b0 = 1104; bc = 880; }
    else if (b < 2016) { in = s1; out = s1o; n = 262144;  b0 = 1984; bc = 32;  }
    else               { in = s2; out = s2o; n = 262144;  b0 = 2016; bc = 32;  }
    int g = bc * 256;
    int i = (b - b0) * 256 + threadIdx.x;
    for (; i + 3 * g < n; i += 4 * g) {
        float4 v0 = in[i], v1 = in[i + g], v2 = in[i + 2 * g], v3 = in[i + 3 * g];
        out[i]         = pack4(v0);
        out[i + g]     = pack4(v1);
        out[i + 2 * g] = pack4(v2);
        out[i + 3 * g] = pack4(v3);
    }
    for (; i < n; i += g) out[i] = pack4(in[i]);
}

// ---------------- exact fp32 router GEMM, split-K into RKS slices ------------
#define RTM 64
#define RTK 16
__global__ void router_sgemm(const float* __restrict__ A, const float* __restrict__ B)
{
    __shared__ float As[RTK][RTM + 4];
    __shared__ float Bs[RTK][64];
    int tid = threadIdx.x;
    int tx = tid & 15, ty = tid >> 4;
    int bm = blockIdx.y * RTM;
    int z  = blockIdx.z;                        // K slice
    float* Cc = g_part + z * T_TOK * NEXP;
    int la_m = tid >> 2, la_k = (tid & 3) * 4;
    int lb_k = tid >> 4, lb_n = (tid & 15) * 4;
    float acc[4][4];
#pragma unroll
    for (int i = 0; i < 4; i++)
#pragma unroll
        for (int j = 0; j < 4; j++) acc[i][j] = 0.0f;
    const int kbeg = z * (HID / RKS), kend = kbeg + HID / RKS;
    for (int k0 = kbeg; k0 < kend; k0 += RTK) {
        float4 av = *reinterpret_cast<const float4*>(A + (size_t)(bm + la_m) * HID + k0 + la_k);
        As[la_k + 0][la_m] = av.x; As[la_k + 1][la_m] = av.y;
        As[la_k + 2][la_m] = av.z; As[la_k + 3][la_m] = av.w;
        float4 bv = *reinterpret_cast<const float4*>(B + (size_t)(k0 + lb_k) * NEXP + lb_n);
        Bs[lb_k][lb_n + 0] = bv.x; Bs[lb_k][lb_n + 1] = bv.y;
        Bs[lb_k][lb_n + 2] = bv.z; Bs[lb_k][lb_n + 3] = bv.w;
        __syncthreads();
#pragma unroll
        for (int kk = 0; kk < RTK; kk++) {
            float a[4], b[4];
#pragma unroll
            for (int i = 0; i < 4; i++) a[i] = As[kk][ty * 4 + i];
#pragma unroll
            for (int j = 0; j < 4; j++) b[j] = Bs[kk][tx * 4 + j];
#pragma unroll
            for (int i = 0; i < 4; i++)
#pragma unroll
                for (int j = 0; j < 4; j++) acc[i][j] += a[i] * b[j];
        }
        __syncthreads();
    }
#pragma unroll
    for (int i = 0; i < 4; i++)
#pragma unroll
        for (int j = 0; j < 4; j++)
            Cc[(size_t)(bm + ty * 4 + i) * NEXP + tx * 4 + j] = acc[i][j];
}

// ---------------- router top-k / softmax / slot assignment (fused) ----------
__global__ void topk_kernel() {
    int warp = threadIdx.x >> 5, lane = threadIdx.x & 31;
    int t = blockIdx.x * 4 + warp;
    if (t >= T_TOK) return;
    float s0 = 0.0f, s1 = 0.0f;
#pragma unroll
    for (int z = 0; z < RKS; z++) {
        s0 += g_part[z * T_TOK * NEXP + t * NEXP + lane];
        s1 += g_part[z * T_TOK * NEXP + t * NEXP + 32 + lane];
    }
    float m = fmaxf(s0, s1);
#pragma unroll
    for (int o = 16; o; o >>= 1) m = fmaxf(m, __shfl_xor_sync(0xffffffffu, m, o));
    float e0 = expf(s0 - m), e1 = expf(s1 - m);
    float d = e0 + e1;
#pragma unroll
    for (int o = 16; o; o >>= 1) d += __shfl_xor_sync(0xffffffffu, d, o);
    float p0 = e0 / d, p1 = e1 / d;

    float mx = fmaxf(p0, p1);
#pragma unroll
    for (int o = 16; o; o >>= 1) mx = fmaxf(mx, __shfl_xor_sync(0xffffffffu, mx, o));
    int cand = 0x7fffffff;
    if (p0 == mx) cand = lane;
    if (p1 == mx) cand = min(cand, lane + 32);
#pragma unroll
    for (int o = 16; o; o >>= 1) cand = min(cand, __shfl_xor_sync(0xffffffffu, cand, o));
    int i1 = cand; float v1 = mx;

    float q0 = (lane == i1) ? -1e30f : p0;
    float q1 = (lane + 32 == i1) ? -1e30f : p1;
    float mx2 = fmaxf(q0, q1);
#pragma unroll
    for (int o = 16; o; o >>= 1) mx2 = fmaxf(mx2, __shfl_xor_sync(0xffffffffu, mx2, o));
    int cand2 = 0x7fffffff;
    if (q0 == mx2) cand2 = lane;
    if (q1 == mx2) cand2 = min(cand2, lane + 32);
#pragma unroll
    for (int o = 16; o; o >>= 1) cand2 = min(cand2, __shfl_xor_sync(0xffffffffu, cand2, o));
    int i2 = cand2; float v2 = mx2;

    if (lane == 0) {
        g_topv[t * 2 + 0] = v1;
        g_topv[t * 2 + 1] = v2;
        int p1s = atomicAdd(&g_listcnt[i1], 1);
        if (p1s < CAP) g_assign[i1 * CAP + p1s] = t * 2;
        int p2s = atomicAdd(&g_listcnt[i2], 1);
        if (p2s < CAP) g_assign[i2 * CAP + p2s] = t * 2 + 1;
    }
    atomicAdd(&g_psum[lane], p0);
    atomicAdd(&g_psum[lane + 32], p1);
}

// ---------------- fp16 single-pass mma.sync GEMM -----------------------------
// C[M,N] = A[M,K] @ B[K,N]   (B row-major [K][N], loaded via ldmatrix.trans)
// CTA 128x128, K-chunk 64, 3-stage cp.async pipeline, 8 warps (warp tile 64x32).
// Mainloop: all 6 fragment LDSMs issued before any MMA (latency cover).
// EPI: 0 = gelu -> fp16 out, 1 = f32 store, 2 = atomic combine into out[token]
#define STAGE_BYTES 32768   // A 16K + B 16K
#define MISC_OFF    98304   // 3 stages

template<int EPI, bool GATHER, bool EXPERT>
__global__ void __launch_bounds__(256, 2)
mma_gemm(const __half* __restrict__ A, int lda, long aBatch,
         const __half* __restrict__ B, int ldb, long bBatch,
         __half* __restrict__ outH, float* __restrict__ outF, int ldc, long cBatch,
         int M, int Kd)
{
    extern __shared__ char smem[];
    const int tid = threadIdx.x;
    const int lane = tid & 31, warp = tid >> 5;
    const int wm = warp & 1, wn = warp >> 1;
    const int bm = blockIdx.y * 128, bn = blockIdx.x * 128;

    int e = 0, cnt = M;
    if (EXPERT) {
        e = blockIdx.z;
        cnt = min(g_listcnt[e], CAP);
        if (bm >= cnt) return;
        if (aBatch) A += (size_t)e * aBatch;
        B += (size_t)e * bBatch;
        if (EPI == 0) outH += (size_t)e * cBatch;
    }

    int*   tok = (int*)(smem + MISC_OFF);
    float* pw  = (float*)(smem + MISC_OFF + 512);
    if ((GATHER || EPI == 2) && tid < 128) {
        int idx = min(bm + tid, cnt - 1);
        int a = g_assign[e * CAP + idx];
        tok[tid] = a >> 1;                    // token (KTOP=2)
        pw[tid]  = g_topv[a];
    }
    __syncthreads();

    uint32_t sb = smem_u32(smem);
    const int NC = Kd >> 6;

    // hoisted per-thread cp.async source offsets (uint32: all intra-buffer)
    const char* Ab = (const char*)A;
    const char* Bb = (const char*)B;
    uint32_t offA[4]; uint32_t soA[4];
    uint32_t offB[4]; uint32_t soB[4];
#pragma unroll
    for (int j = 0; j < 4; j++) {
        int p = tid + j * 256;
        int r = p >> 3, q = p & 7;                 // A: 128 rows x 8 vec16
        uint32_t row = GATHER ? (uint32_t)tok[r] : (uint32_t)(bm + r);
        offA[j] = (row * (uint32_t)lda + q * 8) * 2;
        soA[j]  = SWA((uint32_t)(r * 128 + q * 16));
        int kr = p >> 4, nq = p & 15;              // B: 64 rows x 16 vec16
        offB[j] = ((uint32_t)kr * (uint32_t)ldb + bn + nq * 8) * 2;
        soB[j]  = 16384 + SWB((uint32_t)(kr * 256 + nq * 16));
    }
    const uint32_t stepA = 64 * 2;
    const uint32_t stepB = (uint32_t)64 * ldb * 2;

    // hoisted ldmatrix address invariants:
    //   A: addr(kk) = sA + (aInv[mt] ^ (kk*32))   (XOR legal: no carries into mask bits)
    //   B: addr(kk) = sA + bInv[ntp] + kk*4096    (mask depends only on lane&15)
    uint32_t aInv[4], bInv[2];
#pragma unroll
    for (int mt = 0; mt < 4; mt++) {
        uint32_t row = wm * 64 + mt * 16 + (lane & 15);
        uint32_t col = (lane >> 4) << 4;
        aInv[mt] = row * 128 + (col ^ ((row & 7) << 4));
    }
#pragma unroll
    for (int ntp = 0; ntp < 2; ntp++) {
        uint32_t o = (lane & 15) * 256 + (wn * 32 + ntp * 16 + ((lane >> 4) << 3)) * 2;
        bInv[ntp] = 16384 + SWB(o);
    }

#define ISSUE_CHUNK(ss) do {                                                  \
    uint32_t st_ = sb + (ss) * STAGE_BYTES;                                   \
    _Pragma("unroll")                                                         \
    for (int j = 0; j < 4; j++) {                                             \
        cp16(st_ + soA[j], Ab + offA[j]);  offA[j] += stepA;                  \
        cp16(st_ + soB[j], Bb + offB[j]);  offB[j] += stepB;                  \
    } } while (0)

    ISSUE_CHUNK(0); CP_COMMIT();
    ISSUE_CHUNK(1); CP_COMMIT();

    float acc[4][4][4];
#pragma unroll
    for (int a = 0; a < 4; a++)
#pragma unroll
        for (int b = 0; b < 4; b++)
#pragma unroll
            for (int c = 0; c < 4; c++) acc[a][b][c] = 0.0f;

    for (int c = 0; c < NC; ++c) {
        CP_WAIT1();
        __syncthreads();
        if (c + 2 < NC) { ISSUE_CHUNK((c + 2) % 3); }
        CP_COMMIT();
        uint32_t sA = sb + (c % 3) * STAGE_BYTES;
#pragma unroll
        for (int kk = 0; kk < 4; kk++) {
            uint32_t af[4][4], bf[2][4];
            // all 6 LDSMs up-front: issue stream covers operand latency
            ldm_x4 (sA + (aInv[0] ^ (kk * 32)), af[0][0], af[0][1], af[0][2], af[0][3]);
            ldm_x4t(sA + bInv[0] + kk * 4096,   bf[0][0], bf[0][1], bf[0][2], bf[0][3]);
            ldm_x4 (sA + (aInv[1] ^ (kk * 32)), af[1][0], af[1][1], af[1][2], af[1][3]);
            ldm_x4t(sA + bInv[1] + kk * 4096,   bf[1][0], bf[1][1], bf[1][2], bf[1][3]);
            ldm_x4 (sA + (aInv[2] ^ (kk * 32)), af[2][0], af[2][1], af[2][2], af[2][3]);
            ldm_x4 (sA + (aInv[3] ^ (kk * 32)), af[3][0], af[3][1], af[3][2], af[3][3]);
#pragma unroll
            for (int ntp = 0; ntp < 2; ntp++)
#pragma unroll
                for (int mt = 0; mt < 4; mt++) {
                    mma_fp16(acc[mt][ntp * 2],     af[mt], bf[ntp][0], bf[ntp][1]);
                    mma_fp16(acc[mt][ntp * 2 + 1], af[mt], bf[ntp][2], bf[ntp][3]);
                }
        }
    }
#undef ISSUE_CHUNK

    const int gr = lane >> 2, gc = (lane & 3) * 2;
    if (EPI == 2) {
        __syncthreads();
        float* tile = (float*)smem;   // 128x128 f32 = 64KB
#pragma unroll
        for (int mt = 0; mt < 4; mt++)
#pragma unroll
            for (int nt = 0; nt < 4; nt++)
#pragma unroll
                for (int h = 0; h < 2; h++) {
                    int rl = wm * 64 + mt * 16 + gr + h * 8;
                    int cl = wn * 32 + nt * 8 + gc;
                    *reinterpret_cast<float2*>(&tile[rl * 128 + cl]) =
                        make_float2(acc[mt][nt][2 * h], acc[mt][nt][2 * h + 1]);
                }
        __syncthreads();
        for (int r = warp; r < 128; r += 8) {
            if (bm + r < cnt) {
                float p = pw[r];
                float* base = outF + (size_t)tok[r] * HID + bn;
                for (int cc = lane; cc < 128; cc += 32)
                    atomicAdd(base + cc, p * tile[r * 128 + cc]);
            }
        }
    } else {
#pragma unroll
        for (int mt = 0; mt < 4; mt++)
#pragma unroll
            for (int nt = 0; nt < 4; nt++)
#pragma unroll
                for (int h = 0; h < 2; h++) {
                    int r = bm + wm * 64 + mt * 16 + gr + h * 8;
                    if (r >= cnt) continue;
                    int col = bn + wn * 32 + nt * 8 + gc;
                    if (EPI == 0) {
                        __half2 hv = __floats2half2_rn(gelu_f(acc[mt][nt][2 * h]),
                                                       gelu_f(acc[mt][nt][2 * h + 1]));
                        *reinterpret_cast<__half2*>(outH + (size_t)r * ldc + col) = hv;
                    } else {
                        *reinterpret_cast<float2*>(outF + (size_t)r * ldc + col) =
                            make_float2(acc[mt][nt][2 * h], acc[mt][nt][2 * h + 1]);
                    }
                }
    }
}

// ---------------- aux loss (listcnt doubles as pre-capacity counts) ----------
__global__ void aux_kernel(float* __restrict__ out, int out_size)
{
    __shared__ float vals[NEXP];
    int i = threadIdx.x;
    if (i < NEXP) {
        float f = (float)g_listcnt[i] / (float)(T_TOK * KTOP);
        float P = g_psum[i] / (float)T_TOK;
        vals[i] = f * P;
    }
    __syncthreads();
    if (i == 0) {
        float s = 0.0f;
        for (int j = 0; j < NEXP; j++) s += vals[j];
        if (out_size > T_TOK * HID) out[T_TOK * HID] = 0.01f * (float)NEXP * s;
    }
}

// ---------------- launch ----------------
extern "C" void kernel_launch(void* const* d_in, const int* in_sizes, int n_in,
                              void* d_out, int out_size)
{
    const float* x        = (const float*)d_in[0];  // [T,H]
    const float* w_router = (const float*)d_in[1];  // [H,E]
    const float* w1       = (const float*)d_in[2];  // [E,H,F]
    const float* w2       = (const float*)d_in[3];  // [E,F,H]
    const float* ws1      = (const float*)d_in[4];  // [H,SF]
    const float* ws2      = (const float*)d_in[5];  // [SF,H]
    float* out = (float*)d_out;

    __half *xh, *w1h, *w2h, *ws1h, *ws2h, *hbuf, *sbuf;
    cudaGetSymbolAddress((void**)&xh,  g_xh);
    cudaGetSymbolAddress((void**)&w1h, g_w1h);
    cudaGetSymbolAddress((void**)&w2h, g_w2h);
    cudaGetSymbolAddress((void**)&ws1h, g_ws1h);
    cudaGetSymbolAddress((void**)&ws2h, g_ws2h);
    cudaGetSymbolAddress((void**)&hbuf, g_h);
    cudaGetSymbolAddress((void**)&sbuf, g_s);

    const int SMB = MISC_OFF + 1024;   // 3 stages + tok/pw
    cudaFuncSetAttribute(mma_gemm<0, true,  true >, cudaFuncAttributeMaxDynamicSharedMemorySize, SMB);
    cudaFuncSetAttribute(mma_gemm<2, false, true >, cudaFuncAttributeMaxDynamicSharedMemorySize, SMB);
    cudaFuncSetAttribute(mma_gemm<0, false, false>, cudaFuncAttributeMaxDynamicSharedMemorySize, SMB);
    cudaFuncSetAttribute(mma_gemm<1, false, false>, cudaFuncAttributeMaxDynamicSharedMemorySize, SMB);

    // ---- merged prepass (all conversions + bookkeeping zero) ----
    cvt_all<<<2048, 256>>>((const float4*)x,   (uint2*)xh,
                           (const float4*)w1,  (uint2*)w1h,
                           (const float4*)w2,  (uint2*)w2h,
                           (const float4*)ws1, (uint2*)ws1h,
                           (const float4*)ws2, (uint2*)ws2h);

    // ---- router (exact fp32, split-K x4) + fused routing ----
    router_sgemm<<<dim3(1, T_TOK / RTM, RKS), 256>>>(x, w_router);
    topk_kernel<<<T_TOK / 4, 128>>>();

    // ---- shared expert (writes base of out) ----
    mma_gemm<0, false, false><<<dim3(SFFN / 128, T_TOK / 128), 256, SMB>>>(
        xh, HID, 0, ws1h, SFFN, 0, sbuf, nullptr, SFFN, 0, T_TOK, HID);
    mma_gemm<1, false, false><<<dim3(HID / 128, T_TOK / 128), 256, SMB>>>(
        sbuf, SFFN, 0, ws2h, HID, 0, nullptr, out, HID, 0, T_TOK, SFFN);

    // ---- expert MLP; gemm2 atomically combines into out ----
    mma_gemm<0, true, true><<<dim3(FFN / 128, CAP / 128, NEXP), 256, SMB>>>(
        xh, HID, 0, w1h, FFN, (long)HID * FFN, hbuf, nullptr, FFN, (long)CAP * FFN,
        CAP, HID);
    mma_gemm<2, false, true><<<dim3(HID / 128, CAP / 128, NEXP), 256, SMB>>>(
        hbuf, FFN, (long)CAP * FFN, w2h, HID, (long)FFN * HID,
        nullptr, out, HID, 0, CAP, FFN);

    aux_kernel<<<1, 64>>>(out, out_size);
}

// round 15
// speedup vs baseline: 1.0425x; 1.0161x over previous
#include <cuda_runtime.h>
#include <cuda_fp16.h>
#include <math.h>
#include <stdint.h>

// ---------------- problem constants ----------------
#define T_TOK 8192
#define HID   1024
#define NEXP  64
#define KTOP  2
#define CAP   1024
#define FFN   512
#define SFFN  1024
#define NASSIGN (T_TOK*KTOP)
#define RKS   4            // router K slices

// ---------------- helpers (compute_103-safe PTX only) ----------------
__device__ __forceinline__ uint32_t smem_u32(const void* p) {
    uint32_t a;
    asm("{ .reg .u64 t; cvta.to.shared.u64 t, %1; cvt.u32.u64 %0, t; }" : "=r"(a) : "l"(p));
    return a;
}
__device__ __forceinline__ void ldm_x4(uint32_t addr, uint32_t& r0, uint32_t& r1,
                                       uint32_t& r2, uint32_t& r3) {
    asm volatile("ldmatrix.sync.aligned.m8n8.x4.shared.b16 {%0,%1,%2,%3}, [%4];"
        : "=r"(r0), "=r"(r1), "=r"(r2), "=r"(r3) : "r"(addr));
}
__device__ __forceinline__ void ldm_x4t(uint32_t addr, uint32_t& r0, uint32_t& r1,
                                        uint32_t& r2, uint32_t& r3) {
    asm volatile("ldmatrix.sync.aligned.m8n8.x4.trans.shared.b16 {%0,%1,%2,%3}, [%4];"
        : "=r"(r0), "=r"(r1), "=r"(r2), "=r"(r3) : "r"(addr));
}
__device__ __forceinline__ void mma_fp16(float* d, const uint32_t* a, uint32_t b0, uint32_t b1) {
    asm volatile("mma.sync.aligned.m16n8k16.row.col.f32.f16.f16.f32 "
        "{%0,%1,%2,%3}, {%4,%5,%6,%7}, {%8,%9}, {%0,%1,%2,%3};"
        : "+f"(d[0]), "+f"(d[1]), "+f"(d[2]), "+f"(d[3])
        : "r"(a[0]), "r"(a[1]), "r"(a[2]), "r"(a[3]), "r"(b0), "r"(b1));
}
__device__ __forceinline__ void cp16(uint32_t dst, const void* src) {
    size_t g = __cvta_generic_to_global(src);
    asm volatile("cp.async.cg.shared.global [%0], [%1], 16;" :: "r"(dst), "l"(g));
}
#define CP_COMMIT() asm volatile("cp.async.commit_group;" ::: "memory")
#define CP_WAIT1()  asm volatile("cp.async.wait_group 1;" ::: "memory")
// A tiles: 128B rows -> chunk[4:6] ^= row&7
#define SWA(o) ((o) ^ (((o) >> 3) & 0x70))
// B tiles: 256B rows -> chunk[4:6] ^= k&7
#define SWB(o) ((o) ^ (((o) >> 4) & 0x70))

// ---------------- scratch (device globals; allocation is forbidden) ----------
__device__ float g_part[RKS * T_TOK * NEXP];       // router split-K partials, 8 MB
__device__ float g_topv[NASSIGN];
__device__ int   g_listcnt[NEXP];
__device__ float g_psum[NEXP];
__device__ int   g_assign[NEXP * CAP];

__device__ __align__(16) __half g_xh[T_TOK * HID];                  // 16 MB
__device__ __align__(16) __half g_w1h[(size_t)NEXP * HID * FFN];    // 64 MB
__device__ __align__(16) __half g_w2h[(size_t)NEXP * FFN * HID];    // 64 MB
__device__ __align__(16) __half g_ws1h[(size_t)HID * SFFN];
__device__ __align__(16) __half g_ws2h[(size_t)SFFN * HID];
__device__ __align__(16) __half g_h[(size_t)NEXP * CAP * FFN];      // 64 MB
__device__ __align__(16) __half g_s[(size_t)T_TOK * SFFN];          // 16 MB

// fast gelu: tanh via __expf (error ~1e-6, invisible under fp16-pass budget)
__device__ __forceinline__ float gelu_f(float x) {
    float z = 0.7978845608028654f * (x + 0.044715f * x * x * x);
    float t = __expf(2.0f * z);
    float th = 1.0f - 2.0f / (t + 1.0f);
    return 0.5f * x * (1.0f + th);
}

// ---------------- merged prepass: weight fp32 -> fp16 conversions + zeroing --
__device__ __forceinline__ uint2 pack4(float4 v) {
    uint2 r;
    __half2 a = __floats2half2_rn(v.x, v.y);
    __half2 b = __floats2half2_rn(v.z, v.w);
    r.x = *reinterpret_cast<uint32_t*>(&a);
    r.y = *reinterpret_cast<uint32_t*>(&b);
    return r;
}
// block partition over 2960 blocks (=20*148): w1 1440 | w2 1440 | ws1 40 | ws2 40
__global__ void cvt_all(const float4* __restrict__ w1, uint2* __restrict__ w1o,
                        const float4* __restrict__ w2, uint2* __restrict__ w2o,
                        const float4* __restrict__ s1, uint2* __restrict__ s1o,
                        const float4* __restrict__ s2, uint2* __restrict__ s2o)
{
    if (blockIdx.x == 0 && threadIdx.x < NEXP) {
        g_listcnt[threadIdx.x] = 0;
        g_psum[threadIdx.x] = 0.0f;
    }
    int b = blockIdx.x;
    const float4* in; uint2* out; int n, b0, bc;
    if (b < 1440)      { in = w1; out = w1o; n = 8388608; b0 = 0;    bc = 1440; }
    else if (b < 2880) { in = w2; out = w2o; n = 8388608; b0 = 1440; bc = 1440; }
    else if (b < 2920) { in = s1; out = s1o; n = 262144;  b0 = 2880; bc = 40;   }
    else               { in = s2; out = s2o; n = 262144;  b0 = 2920; bc = 40;   }
    int g = bc * 256;
    int i = (b - b0) * 256 + threadIdx.x;
    for (; i + 3 * g < n; i += 4 * g) {
        float4 v0 = in[i], v1 = in[i + g], v2 = in[i + 2 * g], v3 = in[i + 3 * g];
        out[i]         = pack4(v0);
        out[i + g]     = pack4(v1);
        out[i + 2 * g] = pack4(v2);
        out[i + 3 * g] = pack4(v3);
    }
    for (; i < n; i += g) out[i] = pack4(in[i]);
}

// ---------------- exact fp32 router GEMM, split-K; also emits xh (fp16) ------
// Each (row, k) element of x is loaded exactly once across the y*z grid, so
// the As-tile load doubles as the x -> fp16 conversion pass (bit-identical).
#define RTM 64
#define RTK 16
__global__ void router_sgemm(const float* __restrict__ A, const float* __restrict__ B,
                             __half* __restrict__ xh)
{
    __shared__ float As[RTK][RTM + 4];
    __shared__ float Bs[RTK][64];
    int tid = threadIdx.x;
    int tx = tid & 15, ty = tid >> 4;
    int bm = blockIdx.y * RTM;
    int z  = blockIdx.z;                        // K slice
    float* Cc = g_part + z * T_TOK * NEXP;
    int la_m = tid >> 2, la_k = (tid & 3) * 4;
    int lb_k = tid >> 4, lb_n = (tid & 15) * 4;
    float acc[4][4];
#pragma unroll
    for (int i = 0; i < 4; i++)
#pragma unroll
        for (int j = 0; j < 4; j++) acc[i][j] = 0.0f;
    const int kbeg = z * (HID / RKS), kend = kbeg + HID / RKS;
    for (int k0 = kbeg; k0 < kend; k0 += RTK) {
        float4 av = *reinterpret_cast<const float4*>(A + (size_t)(bm + la_m) * HID + k0 + la_k);
        As[la_k + 0][la_m] = av.x; As[la_k + 1][la_m] = av.y;
        As[la_k + 2][la_m] = av.z; As[la_k + 3][la_m] = av.w;
        // emit fp16 x (once per element across the grid)
        {
            uint2 h = pack4(av);
            *reinterpret_cast<uint2*>(xh + (size_t)(bm + la_m) * HID + k0 + la_k) = h;
        }
        float4 bv = *reinterpret_cast<const float4*>(B + (size_t)(k0 + lb_k) * NEXP + lb_n);
        Bs[lb_k][lb_n + 0] = bv.x; Bs[lb_k][lb_n + 1] = bv.y;
        Bs[lb_k][lb_n + 2] = bv.z; Bs[lb_k][lb_n + 3] = bv.w;
        __syncthreads();
#pragma unroll
        for (int kk = 0; kk < RTK; kk++) {
            float a[4], b[4];
#pragma unroll
            for (int i = 0; i < 4; i++) a[i] = As[kk][ty * 4 + i];
#pragma unroll
            for (int j = 0; j < 4; j++) b[j] = Bs[kk][tx * 4 + j];
#pragma unroll
            for (int i = 0; i < 4; i++)
#pragma unroll
                for (int j = 0; j < 4; j++) acc[i][j] += a[i] * b[j];
        }
        __syncthreads();
    }
#pragma unroll
    for (int i = 0; i < 4; i++)
#pragma unroll
        for (int j = 0; j < 4; j++)
            Cc[(size_t)(bm + ty * 4 + i) * NEXP + tx * 4 + j] = acc[i][j];
}

// ---------------- router top-k / softmax / slot assignment (fused) ----------
__global__ void topk_kernel() {
    int warp = threadIdx.x >> 5, lane = threadIdx.x & 31;
    int t = blockIdx.x * 4 + warp;
    if (t >= T_TOK) return;
    float s0 = 0.0f, s1 = 0.0f;
#pragma unroll
    for (int z = 0; z < RKS; z++) {
        s0 += g_part[z * T_TOK * NEXP + t * NEXP + lane];
        s1 += g_part[z * T_TOK * NEXP + t * NEXP + 32 + lane];
    }
    float m = fmaxf(s0, s1);
#pragma unroll
    for (int o = 16; o; o >>= 1) m = fmaxf(m, __shfl_xor_sync(0xffffffffu, m, o));
    float e0 = expf(s0 - m), e1 = expf(s1 - m);
    float d = e0 + e1;
#pragma unroll
    for (int o = 16; o; o >>= 1) d += __shfl_xor_sync(0xffffffffu, d, o);
    float p0 = e0 / d, p1 = e1 / d;

    float mx = fmaxf(p0, p1);
#pragma unroll
    for (int o = 16; o; o >>= 1) mx = fmaxf(mx, __shfl_xor_sync(0xffffffffu, mx, o));
    int cand = 0x7fffffff;
    if (p0 == mx) cand = lane;
    if (p1 == mx) cand = min(cand, lane + 32);
#pragma unroll
    for (int o = 16; o; o >>= 1) cand = min(cand, __shfl_xor_sync(0xffffffffu, cand, o));
    int i1 = cand; float v1 = mx;

    float q0 = (lane == i1) ? -1e30f : p0;
    float q1 = (lane + 32 == i1) ? -1e30f : p1;
    float mx2 = fmaxf(q0, q1);
#pragma unroll
    for (int o = 16; o; o >>= 1) mx2 = fmaxf(mx2, __shfl_xor_sync(0xffffffffu, mx2, o));
    int cand2 = 0x7fffffff;
    if (q0 == mx2) cand2 = lane;
    if (q1 == mx2) cand2 = min(cand2, lane + 32);
#pragma unroll
    for (int o = 16; o; o >>= 1) cand2 = min(cand2, __shfl_xor_sync(0xffffffffu, cand2, o));
    int i2 = cand2; float v2 = mx2;

    if (lane == 0) {
        g_topv[t * 2 + 0] = v1;
        g_topv[t * 2 + 1] = v2;
        int p1s = atomicAdd(&g_listcnt[i1], 1);
        if (p1s < CAP) g_assign[i1 * CAP + p1s] = t * 2;
        int p2s = atomicAdd(&g_listcnt[i2], 1);
        if (p2s < CAP) g_assign[i2 * CAP + p2s] = t * 2 + 1;
    }
    atomicAdd(&g_psum[lane], p0);
    atomicAdd(&g_psum[lane + 32], p1);
}

// ---------------- fp16 single-pass mma.sync GEMM (R14 config, unchanged) -----
// C[M,N] = A[M,K] @ B[K,N]   (B row-major [K][N], loaded via ldmatrix.trans)
// CTA 128x128, K-chunk 64, 3-stage cp.async pipeline, 8 warps (warp tile 64x32).
// Mainloop: all 6 fragment LDSMs issued before any MMA (latency cover).
// EPI: 0 = gelu -> fp16 out, 1 = f32 store, 2 = atomic combine into out[token]
#define STAGE_BYTES 32768   // A 16K + B 16K
#define MISC_OFF    98304   // 3 stages

template<int EPI, bool GATHER, bool EXPERT>
__global__ void __launch_bounds__(256, 2)
mma_gemm(const __half* __restrict__ A, int lda, long aBatch,
         const __half* __restrict__ B, int ldb, long bBatch,
         __half* __restrict__ outH, float* __restrict__ outF, int ldc, long cBatch,
         int M, int Kd)
{
    extern __shared__ char smem[];
    const int tid = threadIdx.x;
    const int lane = tid & 31, warp = tid >> 5;
    const int wm = warp & 1, wn = warp >> 1;
    const int bm = blockIdx.y * 128, bn = blockIdx.x * 128;

    int e = 0, cnt = M;
    if (EXPERT) {
        e = blockIdx.z;
        cnt = min(g_listcnt[e], CAP);
        if (bm >= cnt) return;
        if (aBatch) A += (size_t)e * aBatch;
        B += (size_t)e * bBatch;
        if (EPI == 0) outH += (size_t)e * cBatch;
    }

    int*   tok = (int*)(smem + MISC_OFF);
    float* pw  = (float*)(smem + MISC_OFF + 512);
    if ((GATHER || EPI == 2) && tid < 128) {
        int idx = min(bm + tid, cnt - 1);
        int a = g_assign[e * CAP + idx];
        tok[tid] = a >> 1;                    // token (KTOP=2)
        pw[tid]  = g_topv[a];
    }
    __syncthreads();

    uint32_t sb = smem_u32(smem);
    const int NC = Kd >> 6;

    // hoisted per-thread cp.async source offsets (uint32: all intra-buffer)
    const char* Ab = (const char*)A;
    const char* Bb = (const char*)B;
    uint32_t offA[4]; uint32_t soA[4];
    uint32_t offB[4]; uint32_t soB[4];
#pragma unroll
    for (int j = 0; j < 4; j++) {
        int p = tid + j * 256;
        int r = p >> 3, q = p & 7;                 // A: 128 rows x 8 vec16
        uint32_t row = GATHER ? (uint32_t)tok[r] : (uint32_t)(bm + r);
        offA[j] = (row * (uint32_t)lda + q * 8) * 2;
        soA[j]  = SWA((uint32_t)(r * 128 + q * 16));
        int kr = p >> 4, nq = p & 15;              // B: 64 rows x 16 vec16
        offB[j] = ((uint32_t)kr * (uint32_t)ldb + bn + nq * 8) * 2;
        soB[j]  = 16384 + SWB((uint32_t)(kr * 256 + nq * 16));
    }
    const uint32_t stepA = 64 * 2;
    const uint32_t stepB = (uint32_t)64 * ldb * 2;

    // hoisted ldmatrix address invariants:
    //   A: addr(kk) = sA + (aInv[mt] ^ (kk*32))   (XOR legal: no carries into mask bits)
    //   B: addr(kk) = sA + bInv[ntp] + kk*4096    (mask depends only on lane&15)
    uint32_t aInv[4], bInv[2];
#pragma unroll
    for (int mt = 0; mt < 4; mt++) {
        uint32_t row = wm * 64 + mt * 16 + (lane & 15);
        uint32_t col = (lane >> 4) << 4;
        aInv[mt] = row * 128 + (col ^ ((row & 7) << 4));
    }
#pragma unroll
    for (int ntp = 0; ntp < 2; ntp++) {
        uint32_t o = (lane & 15) * 256 + (wn * 32 + ntp * 16 + ((lane >> 4) << 3)) * 2;
        bInv[ntp] = 16384 + SWB(o);
    }

#define ISSUE_CHUNK(ss) do {                                                  \
    uint32_t st_ = sb + (ss) * STAGE_BYTES;                                   \
    _Pragma("unroll")                                                         \
    for (int j = 0; j < 4; j++) {                                             \
        cp16(st_ + soA[j], Ab + offA[j]);  offA[j] += stepA;                  \
        cp16(st_ + soB[j], Bb + offB[j]);  offB[j] += stepB;                  \
    } } while (0)

    ISSUE_CHUNK(0); CP_COMMIT();
    ISSUE_CHUNK(1); CP_COMMIT();

    float acc[4][4][4];
#pragma unroll
    for (int a = 0; a < 4; a++)
#pragma unroll
        for (int b = 0; b < 4; b++)
#pragma unroll
            for (int c = 0; c < 4; c++) acc[a][b][c] = 0.0f;

    for (int c = 0; c < NC; ++c) {
        CP_WAIT1();
        __syncthreads();
        if (c + 2 < NC) { ISSUE_CHUNK((c + 2) % 3); }
        CP_COMMIT();
        uint32_t sA = sb + (c % 3) * STAGE_BYTES;
#pragma unroll
        for (int kk = 0; kk < 4; kk++) {
            uint32_t af[4][4], bf[2][4];
            // all 6 LDSMs up-front: issue stream covers operand latency
            ldm_x4 (sA + (aInv[0] ^ (kk * 32)), af[0][0], af[0][1], af[0][2], af[0][3]);
            ldm_x4t(sA + bInv[0] + kk * 4096,   bf[0][0], bf[0][1], bf[0][2], bf[0][3]);
            ldm_x4 (sA + (aInv[1] ^ (kk * 32)), af[1][0], af[1][1], af[1][2], af[1][3]);
            ldm_x4t(sA + bInv[1] + kk * 4096,   bf[1][0], bf[1][1], bf[1][2], bf[1][3]);
            ldm_x4 (sA + (aInv[2] ^ (kk * 32)), af[2][0], af[2][1], af[2][2], af[2][3]);
            ldm_x4 (sA + (aInv[3] ^ (kk * 32)), af[3][0], af[3][1], af[3][2], af[3][3]);
#pragma unroll
            for (int ntp = 0; ntp < 2; ntp++)
#pragma unroll
                for (int mt = 0; mt < 4; mt++) {
                    mma_fp16(acc[mt][ntp * 2],     af[mt], bf[ntp][0], bf[ntp][1]);
                    mma_fp16(acc[mt][ntp * 2 + 1], af[mt], bf[ntp][2], bf[ntp][3]);
                }
        }
    }
#undef ISSUE_CHUNK

    const int gr = lane >> 2, gc = (lane & 3) * 2;
    if (EPI == 2) {
        __syncthreads();
        float* tile = (float*)smem;   // 128x128 f32 = 64KB
#pragma unroll
        for (int mt = 0; mt < 4; mt++)
#pragma unroll
            for (int nt = 0; nt < 4; nt++)
#pragma unroll
                for (int h = 0; h < 2; h++) {
                    int rl = wm * 64 + mt * 16 + gr + h * 8;
                    int cl = wn * 32 + nt * 8 + gc;
                    *reinterpret_cast<float2*>(&tile[rl * 128 + cl]) =
                        make_float2(acc[mt][nt][2 * h], acc[mt][nt][2 * h + 1]);
                }
        __syncthreads();
        for (int r = warp; r < 128; r += 8) {
            if (bm + r < cnt) {
                float p = pw[r];
                float* base = outF + (size_t)tok[r] * HID + bn;
                for (int cc = lane; cc < 128; cc += 32)
                    atomicAdd(base + cc, p * tile[r * 128 + cc]);
            }
        }
    } else {
#pragma unroll
        for (int mt = 0; mt < 4; mt++)
#pragma unroll
            for (int nt = 0; nt < 4; nt++)
#pragma unroll
                for (int h = 0; h < 2; h++) {
                    int r = bm + wm * 64 + mt * 16 + gr + h * 8;
                    if (r >= cnt) continue;
                    int col = bn + wn * 32 + nt * 8 + gc;
                    if (EPI == 0) {
                        __half2 hv = __floats2half2_rn(gelu_f(acc[mt][nt][2 * h]),
                                                       gelu_f(acc[mt][nt][2 * h + 1]));
                        *reinterpret_cast<__half2*>(outH + (size_t)r * ldc + col) = hv;
                    } else {
                        *reinterpret_cast<float2*>(outF + (size_t)r * ldc + col) =
                            make_float2(acc[mt][nt][2 * h], acc[mt][nt][2 * h + 1]);
                    }
                }
    }
}

// ---------------- aux loss (listcnt doubles as pre-capacity counts) ----------
__global__ void aux_kernel(float* __restrict__ out, int out_size)
{
    __shared__ float vals[NEXP];
    int i = threadIdx.x;
    if (i < NEXP) {
        float f = (float)g_listcnt[i] / (float)(T_TOK * KTOP);
        float P = g_psum[i] / (float)T_TOK;
        vals[i] = f * P;
    }
    __syncthreads();
    if (i == 0) {
        float s = 0.0f;
        for (int j = 0; j < NEXP; j++) s += vals[j];
        if (out_size > T_TOK * HID) out[T_TOK * HID] = 0.01f * (float)NEXP * s;
    }
}

// ---------------- launch ----------------
extern "C" void kernel_launch(void* const* d_in, const int* in_sizes, int n_in,
                              void* d_out, int out_size)
{
    const float* x        = (const float*)d_in[0];  // [T,H]
    const float* w_router = (const float*)d_in[1];  // [H,E]
    const float* w1       = (const float*)d_in[2];  // [E,H,F]
    const float* w2       = (const float*)d_in[3];  // [E,F,H]
    const float* ws1      = (const float*)d_in[4];  // [H,SF]
    const float* ws2      = (const float*)d_in[5];  // [SF,H]
    float* out = (float*)d_out;

    __half *xh, *w1h, *w2h, *ws1h, *ws2h, *hbuf, *sbuf;
    cudaGetSymbolAddress((void**)&xh,  g_xh);
    cudaGetSymbolAddress((void**)&w1h, g_w1h);
    cudaGetSymbolAddress((void**)&w2h, g_w2h);
    cudaGetSymbolAddress((void**)&ws1h, g_ws1h);
    cudaGetSymbolAddress((void**)&ws2h, g_ws2h);
    cudaGetSymbolAddress((void**)&hbuf, g_h);
    cudaGetSymbolAddress((void**)&sbuf, g_s);

    const int SMB = MISC_OFF + 1024;   // 3 stages + tok/pw
    cudaFuncSetAttribute(mma_gemm<0, true,  true >, cudaFuncAttributeMaxDynamicSharedMemorySize, SMB);
    cudaFuncSetAttribute(mma_gemm<2, false, true >, cudaFuncAttributeMaxDynamicSharedMemorySize, SMB);
    cudaFuncSetAttribute(mma_gemm<0, false, false>, cudaFuncAttributeMaxDynamicSharedMemorySize, SMB);
    cudaFuncSetAttribute(mma_gemm<1, false, false>, cudaFuncAttributeMaxDynamicSharedMemorySize, SMB);

    // ---- merged prepass (weight conversions + bookkeeping zero) ----
    cvt_all<<<2960, 256>>>((const float4*)w1,  (uint2*)w1h,
                           (const float4*)w2,  (uint2*)w2h,
                           (const float4*)ws1, (uint2*)ws1h,
                           (const float4*)ws2, (uint2*)ws2h);

    // ---- router (exact fp32, split-K x4; emits xh as side product) ----
    router_sgemm<<<dim3(1, T_TOK / RTM, RKS), 256>>>(x, w_router, xh);
    topk_kernel<<<T_TOK / 4, 128>>>();

    // ---- shared expert (writes base of out) ----
    mma_gemm<0, false, false><<<dim3(SFFN / 128, T_TOK / 128), 256, SMB>>>(
        xh, HID, 0, ws1h, SFFN, 0, sbuf, nullptr, SFFN, 0, T_TOK, HID);
    mma_gemm<1, false, false><<<dim3(HID / 128, T_TOK / 128), 256, SMB>>>(
        sbuf, SFFN, 0, ws2h, HID, 0, nullptr, out, HID, 0, T_TOK, SFFN);

    // ---- expert MLP; gemm2 atomically combines into out ----
    mma_gemm<0, true, true><<<dim3(FFN / 128, CAP / 128, NEXP), 256, SMB>>>(
        xh, HID, 0, w1h, FFN, (long)HID * FFN, hbuf, nullptr, FFN, (long)CAP * FFN,
        CAP, HID);
    mma_gemm<2, false, true><<<dim3(HID / 128, CAP / 128, NEXP), 256, SMB>>>(
        hbuf, FFN, (long)CAP * FFN, w2h, HID, (long)FFN * HID,
        nullptr, out, HID, 0, CAP, FFN);

    aux_kernel<<<1, 64>>>(out, out_size);
}